// round 5
// baseline (speedup 1.0000x reference)
#include <cuda_runtime.h>
#include <math.h>

#define B_  8
#define T_  10
#define N_  50
#define IN_ 6
#define H_  256
#define K_  4
#define E_  2450           // N*(N-1)
#define BN  400            // B*N
#define BE  19600          // B*E

#define GRID    296
#define THREADS 128

// ---------------- scratch (device globals) ----------------------------------
__device__ float g_hidden[BN * H_];
__device__ float g_ins[BN * IN_];
__device__ float g_U[6 * BN * H_];          // (type-1)*2 + {recv=0,send=1}
__device__ float g_msgs[BE * H_];
__device__ float g_agg[BN * H_];
__device__ float g_gru[3 * BN * H_];
__device__ float g_p1[BN * H_];
__device__ float g_p2[BN * H_];

// ---------------- grid barrier state -----------------------------------------
__device__ unsigned g_bar_count = 0;
__device__ unsigned g_bar_epoch = 0;

// ---------------- tf32 mma helpers -------------------------------------------
__device__ __forceinline__ unsigned tf32c(float x) {
    unsigned r; asm("cvt.rna.tf32.f32 %0, %1;" : "=r"(r) : "f"(x)); return r;
}
__device__ __forceinline__ void mma8(float c[4], const unsigned a[4],
                                     unsigned b0, unsigned b1) {
    asm volatile(
        "mma.sync.aligned.m16n8k8.row.col.f32.tf32.tf32.f32 "
        "{%0,%1,%2,%3}, {%4,%5,%6,%7}, {%8,%9}, {%0,%1,%2,%3};"
        : "+f"(c[0]), "+f"(c[1]), "+f"(c[2]), "+f"(c[3])
        : "r"(a[0]), "r"(a[1]), "r"(a[2]), "r"(a[3]), "r"(b0), "r"(b1));
}
__device__ __forceinline__ float sigmoidf_(float x) { return 1.f / (1.f + expf(-x)); }

// ---------------- tf32 GEMM tile: 64(M) x 128(N), 128 threads ----------------
__device__ void tc_tile(
    const float* __restrict__ A, int lda,
    const float* __restrict__ W, int ldw,
    const float* __restrict__ bias,
    float* __restrict__ C, int ldc,
    int M, int Kdim, int row0, int col0, int act,
    unsigned As[64][20], unsigned Ws[128][20])
{
    const int tid = threadIdx.x;
    const int lane = tid & 31, wid = tid >> 5;
    const int gid = lane >> 2, tig = lane & 3;
    const int wm0 = (wid >> 1) * 32, wn0 = (wid & 1) * 64;
    const int ar = tid >> 1, akq = (tid & 1) * 8;
    const int wn = tid;

    float acc[2][8][4];
#pragma unroll
    for (int mi = 0; mi < 2; mi++)
#pragma unroll
        for (int ni = 0; ni < 8; ni++)
#pragma unroll
            for (int j = 0; j < 4; j++) acc[mi][ni][j] = 0.f;

    int arow = row0 + ar; if (arow >= M) arow = M - 1;
    const float* Ap = A + (size_t)arow * lda + akq;
    const float* Wp = W + (size_t)(col0 + wn) * ldw;

    float4 pa0, pa1, pw0, pw1, pw2, pw3;
    pa0 = *(const float4*)(Ap);     pa1 = *(const float4*)(Ap + 4);
    pw0 = *(const float4*)(Wp);     pw1 = *(const float4*)(Wp + 4);
    pw2 = *(const float4*)(Wp + 8); pw3 = *(const float4*)(Wp + 12);

    const int nchunks = Kdim / 16;
#pragma unroll 1
    for (int c = 0; c < nchunks; c++) {
        __syncthreads();
        uint4 av0, av1;
        av0.x = tf32c(pa0.x); av0.y = tf32c(pa0.y); av0.z = tf32c(pa0.z); av0.w = tf32c(pa0.w);
        av1.x = tf32c(pa1.x); av1.y = tf32c(pa1.y); av1.z = tf32c(pa1.z); av1.w = tf32c(pa1.w);
        *(uint4*)&As[ar][akq]     = av0;
        *(uint4*)&As[ar][akq + 4] = av1;
        uint4 w0v, w1v, w2v, w3v;
        w0v.x = tf32c(pw0.x); w0v.y = tf32c(pw0.y); w0v.z = tf32c(pw0.z); w0v.w = tf32c(pw0.w);
        w1v.x = tf32c(pw1.x); w1v.y = tf32c(pw1.y); w1v.z = tf32c(pw1.z); w1v.w = tf32c(pw1.w);
        w2v.x = tf32c(pw2.x); w2v.y = tf32c(pw2.y); w2v.z = tf32c(pw2.z); w2v.w = tf32c(pw2.w);
        w3v.x = tf32c(pw3.x); w3v.y = tf32c(pw3.y); w3v.z = tf32c(pw3.z); w3v.w = tf32c(pw3.w);
        *(uint4*)&Ws[wn][0]  = w0v;
        *(uint4*)&Ws[wn][4]  = w1v;
        *(uint4*)&Ws[wn][8]  = w2v;
        *(uint4*)&Ws[wn][12] = w3v;
        __syncthreads();
        if (c + 1 < nchunks) {
            int k0 = (c + 1) * 16;
            pa0 = *(const float4*)(Ap + k0);     pa1 = *(const float4*)(Ap + k0 + 4);
            pw0 = *(const float4*)(Wp + k0);     pw1 = *(const float4*)(Wp + k0 + 4);
            pw2 = *(const float4*)(Wp + k0 + 8); pw3 = *(const float4*)(Wp + k0 + 12);
        }
#pragma unroll
        for (int kk = 0; kk < 16; kk += 8) {
            unsigned a0[4], a1[4];
            a0[0] = As[wm0 + gid][kk + tig];
            a0[1] = As[wm0 + gid + 8][kk + tig];
            a0[2] = As[wm0 + gid][kk + tig + 4];
            a0[3] = As[wm0 + gid + 8][kk + tig + 4];
            a1[0] = As[wm0 + 16 + gid][kk + tig];
            a1[1] = As[wm0 + 24 + gid][kk + tig];
            a1[2] = As[wm0 + 16 + gid][kk + tig + 4];
            a1[3] = As[wm0 + 24 + gid][kk + tig + 4];
#pragma unroll
            for (int ni = 0; ni < 8; ni++) {
                int nr = wn0 + ni * 8 + gid;
                unsigned b0 = Ws[nr][kk + tig];
                unsigned b1 = Ws[nr][kk + tig + 4];
                mma8(acc[0][ni], a0, b0, b1);
                mma8(acc[1][ni], a1, b0, b1);
            }
        }
    }

#pragma unroll
    for (int mi = 0; mi < 2; mi++) {
        int r = row0 + wm0 + mi * 16 + gid;
#pragma unroll
        for (int ni = 0; ni < 8; ni++) {
            int cb = col0 + wn0 + ni * 8 + tig * 2;
            float b0 = 0.f, b1 = 0.f;
            if (bias) { b0 = bias[cb]; b1 = bias[cb + 1]; }
            float v0 = acc[mi][ni][0] + b0, v1 = acc[mi][ni][1] + b1;
            float v2 = acc[mi][ni][2] + b0, v3 = acc[mi][ni][3] + b1;
            if (act == 1) {
                v0 = fmaxf(v0, 0.f); v1 = fmaxf(v1, 0.f);
                v2 = fmaxf(v2, 0.f); v3 = fmaxf(v3, 0.f);
            }
            if (r < M)     *(float2*)(C + (size_t)r * ldc + cb)       = make_float2(v0, v1);
            if (r + 8 < M) *(float2*)(C + (size_t)(r + 8) * ldc + cb) = make_float2(v2, v3);
        }
    }
}

// ---------------- fused edge-message tile -------------------------------------
__device__ void msgs_tile(
    const float* __restrict__ msg_w2,
    const float* __restrict__ msg_b1,
    const float* __restrict__ msg_b2,
    const float* __restrict__ edges, int t,
    int row0, int col0,
    unsigned As[64][20], unsigned Ws[128][20],
    float relw[64], float b2s[128],
    int rrow[64], int srow[64], int eoff[64])
{
    const int tid = threadIdx.x;
    const int lane = tid & 31, wid = tid >> 5;
    const int gid = lane >> 2, tig = lane & 3;
    const int wm0 = (wid >> 1) * 32, wn0 = (wid & 1) * 64;

    __syncthreads();   // protect smem reuse from previous tile
    if (tid < 64) {
        int r = row0 + tid;
        int valid = (r < BE);
        if (!valid) r = BE - 1;
        int b = r / E_;
        int e = r - b * E_;
        int send = e / 49, rr2 = e - send * 49;
        int recv = rr2 + (rr2 >= send);
        srow[tid] = b * N_ + send;
        rrow[tid] = b * N_ + recv;
        eoff[tid] = valid ? (((b * T_ + t) * E_ + e) * K_) : -1;
    }
    __syncthreads();

    const int ar  = tid >> 1;
    const int akq = (tid & 1) * 8;
    const int wn  = tid;

    float tot[2][8][4];
#pragma unroll
    for (int mi = 0; mi < 2; mi++)
#pragma unroll
        for (int ni = 0; ni < 8; ni++)
#pragma unroll
            for (int j = 0; j < 4; j++) tot[mi][ni][j] = 0.f;

    for (int z = 0; z < 3; z++) {
        const int type = z + 1;
        __syncthreads();
        if (tid < 64)
            relw[tid] = (eoff[tid] >= 0) ? edges[eoff[tid] + type] * (1.f / 3.f) : 0.f;
        b2s[tid] = msg_b2[(size_t)type * H_ + col0 + tid];

        float acc[2][8][4];
#pragma unroll
        for (int mi = 0; mi < 2; mi++)
#pragma unroll
            for (int ni = 0; ni < 8; ni++)
#pragma unroll
                for (int j = 0; j < 4; j++) acc[mi][ni][j] = 0.f;

        const float* Ur = g_U + ((size_t)(2 * z) * BN + rrow[ar]) * H_ + akq;
        const float* Us = g_U + ((size_t)(2 * z + 1) * BN + srow[ar]) * H_ + akq;
        const float* Wb = msg_w2 + ((size_t)type * H_ + (col0 + wn)) * H_;
        const float* B1 = msg_b1 + (size_t)type * H_ + akq;

        float4 pu0, pu1, ps0, ps1, pw0, pw1, pw2, pw3, pb0, pb1;
        pu0 = *(const float4*)(Ur);     pu1 = *(const float4*)(Ur + 4);
        ps0 = *(const float4*)(Us);     ps1 = *(const float4*)(Us + 4);
        pw0 = *(const float4*)(Wb);     pw1 = *(const float4*)(Wb + 4);
        pw2 = *(const float4*)(Wb + 8); pw3 = *(const float4*)(Wb + 12);
        pb0 = *(const float4*)(B1);     pb1 = *(const float4*)(B1 + 4);

#pragma unroll 1
        for (int c = 0; c < 16; c++) {
            __syncthreads();
            uint4 a0v, a1v;
            a0v.x = tf32c(tanhf(pu0.x + ps0.x + pb0.x));
            a0v.y = tf32c(tanhf(pu0.y + ps0.y + pb0.y));
            a0v.z = tf32c(tanhf(pu0.z + ps0.z + pb0.z));
            a0v.w = tf32c(tanhf(pu0.w + ps0.w + pb0.w));
            a1v.x = tf32c(tanhf(pu1.x + ps1.x + pb1.x));
            a1v.y = tf32c(tanhf(pu1.y + ps1.y + pb1.y));
            a1v.z = tf32c(tanhf(pu1.z + ps1.z + pb1.z));
            a1v.w = tf32c(tanhf(pu1.w + ps1.w + pb1.w));
            *(uint4*)&As[ar][akq]     = a0v;
            *(uint4*)&As[ar][akq + 4] = a1v;
            uint4 w0v, w1v, w2v, w3v;
            w0v.x = tf32c(pw0.x); w0v.y = tf32c(pw0.y); w0v.z = tf32c(pw0.z); w0v.w = tf32c(pw0.w);
            w1v.x = tf32c(pw1.x); w1v.y = tf32c(pw1.y); w1v.z = tf32c(pw1.z); w1v.w = tf32c(pw1.w);
            w2v.x = tf32c(pw2.x); w2v.y = tf32c(pw2.y); w2v.z = tf32c(pw2.z); w2v.w = tf32c(pw2.w);
            w3v.x = tf32c(pw3.x); w3v.y = tf32c(pw3.y); w3v.z = tf32c(pw3.z); w3v.w = tf32c(pw3.w);
            *(uint4*)&Ws[wn][0]  = w0v;
            *(uint4*)&Ws[wn][4]  = w1v;
            *(uint4*)&Ws[wn][8]  = w2v;
            *(uint4*)&Ws[wn][12] = w3v;
            __syncthreads();
            if (c < 15) {
                int k0 = (c + 1) * 16;
                pu0 = *(const float4*)(Ur + k0);     pu1 = *(const float4*)(Ur + k0 + 4);
                ps0 = *(const float4*)(Us + k0);     ps1 = *(const float4*)(Us + k0 + 4);
                pw0 = *(const float4*)(Wb + k0);     pw1 = *(const float4*)(Wb + k0 + 4);
                pw2 = *(const float4*)(Wb + k0 + 8); pw3 = *(const float4*)(Wb + k0 + 12);
                pb0 = *(const float4*)(B1 + k0);     pb1 = *(const float4*)(B1 + k0 + 4);
            }
#pragma unroll
            for (int kk = 0; kk < 16; kk += 8) {
                unsigned a0[4], a1[4];
                a0[0] = As[wm0 + gid][kk + tig];
                a0[1] = As[wm0 + gid + 8][kk + tig];
                a0[2] = As[wm0 + gid][kk + tig + 4];
                a0[3] = As[wm0 + gid + 8][kk + tig + 4];
                a1[0] = As[wm0 + 16 + gid][kk + tig];
                a1[1] = As[wm0 + 24 + gid][kk + tig];
                a1[2] = As[wm0 + 16 + gid][kk + tig + 4];
                a1[3] = As[wm0 + 24 + gid][kk + tig + 4];
#pragma unroll
                for (int ni = 0; ni < 8; ni++) {
                    int nr = wn0 + ni * 8 + gid;
                    unsigned b0 = Ws[nr][kk + tig];
                    unsigned b1 = Ws[nr][kk + tig + 4];
                    mma8(acc[0][ni], a0, b0, b1);
                    mma8(acc[1][ni], a1, b0, b1);
                }
            }
        }

#pragma unroll
        for (int mi = 0; mi < 2; mi++) {
            float rl0 = relw[wm0 + mi * 16 + gid];
            float rl1 = relw[wm0 + mi * 16 + gid + 8];
#pragma unroll
            for (int ni = 0; ni < 8; ni++) {
                int cl = wn0 + ni * 8 + tig * 2;
                float bb0 = b2s[cl], bb1 = b2s[cl + 1];
                tot[mi][ni][0] += tanhf(acc[mi][ni][0] + bb0) * rl0;
                tot[mi][ni][1] += tanhf(acc[mi][ni][1] + bb1) * rl0;
                tot[mi][ni][2] += tanhf(acc[mi][ni][2] + bb0) * rl1;
                tot[mi][ni][3] += tanhf(acc[mi][ni][3] + bb1) * rl1;
            }
        }
    }

#pragma unroll
    for (int mi = 0; mi < 2; mi++) {
        int r = row0 + wm0 + mi * 16 + gid;
#pragma unroll
        for (int ni = 0; ni < 8; ni++) {
            int cb = col0 + wn0 + ni * 8 + tig * 2;
            if (r < BE)
                *(float2*)(g_msgs + (size_t)r * H_ + cb) =
                    make_float2(tot[mi][ni][0], tot[mi][ni][1]);
            if (r + 8 < BE)
                *(float2*)(g_msgs + (size_t)(r + 8) * H_ + cb) =
                    make_float2(tot[mi][ni][2], tot[mi][ni][3]);
        }
    }
}

// ---------------- THE persistent kernel ---------------------------------------
__global__ __launch_bounds__(THREADS)
void graph_rnn_persistent(
    const float* __restrict__ inputs,
    const float* __restrict__ edges,
    const float* __restrict__ msg_w1, const float* __restrict__ msg_b1,
    const float* __restrict__ msg_w2, const float* __restrict__ msg_b2,
    const float* __restrict__ w_hr, const float* __restrict__ w_hi,
    const float* __restrict__ w_hh,
    const float* __restrict__ w_ir, const float* __restrict__ b_ir,
    const float* __restrict__ w_ii, const float* __restrict__ b_ii,
    const float* __restrict__ w_in, const float* __restrict__ b_in,
    const float* __restrict__ w_o1, const float* __restrict__ b_o1,
    const float* __restrict__ w_o2, const float* __restrict__ b_o2,
    const float* __restrict__ w_o3, const float* __restrict__ b_o3,
    float* __restrict__ out)
{
    __shared__ unsigned As[64][20];
    __shared__ unsigned Ws[128][20];
    __shared__ float relw[64];
    __shared__ float b2s[128];
    __shared__ int rrow[64], srow[64], eoff[64];
    __shared__ float part[256];
    __shared__ unsigned s_base, s_ep;

    const int tid = threadIdx.x;
    const int bid = blockIdx.x;
    const int gthread = bid * THREADS + tid;

    if (tid == 0) {
        s_base = *(volatile unsigned*)&g_bar_epoch;  // replay-safe epoch base
        s_ep = 0;
    }
    __syncthreads();

    // grid barrier lambda-equivalent
    auto gbar = [&]() {
        __syncthreads();
        if (tid == 0) {
            unsigned target = s_base + (++s_ep);
            __threadfence();
            unsigned old = atomicAdd(&g_bar_count, 1);
            if (old == GRID - 1) {
                g_bar_count = 0;
                __threadfence();
                atomicExch(&g_bar_epoch, target);
            } else {
                unsigned e;
                do {
                    asm volatile("ld.acquire.gpu.u32 %0, [%1];"
                                 : "=r"(e) : "l"(&g_bar_epoch));
                } while ((int)(e - target) < 0);
            }
            __threadfence();
        }
        __syncthreads();
    };

    // ---- init: hidden = 0, ins = inputs[:, 0] ----
    for (int idx = gthread; idx < BN * H_; idx += GRID * THREADS) g_hidden[idx] = 0.f;
    for (int idx = gthread; idx < BN * IN_; idx += GRID * THREADS) {
        int row = idx / IN_, c = idx % IN_;
        int b = row / N_, n = row % N_;
        g_ins[idx] = inputs[(((size_t)b * T_ + 0) * N_ + n) * IN_ + c];
    }
    gbar();

    for (int t = 0; t < T_; t++) {
        // ---- phase 1: Ur/Us (84 tiles: z 6, x 7, y 2) ----
        for (int tile = bid; tile < 84; tile += GRID) {
            int z = tile / 14, rem = tile - z * 14;
            int x = rem >> 1, y = rem & 1;
            int it = z >> 1, rs = z & 1;
            const float* W = msg_w1 + (size_t)(it + 1) * H_ * 2 * H_ + rs * H_;
            tc_tile(g_hidden, H_, W, 2 * H_, nullptr,
                    g_U + (size_t)z * BN * H_, H_,
                    BN, H_, x * 64, y * 128, 0, As, Ws);
        }
        gbar();

        // ---- phase 2: edge messages (614 tiles: x 307, y 2) ----
        for (int tile = bid; tile < 614; tile += GRID) {
            int x = tile >> 1, y = tile & 1;
            msgs_tile(msg_w2, msg_b1, msg_b2, edges, t,
                      x * 64, y * 128, As, Ws, relw, b2s, rrow, srow, eoff);
        }
        gbar();

        // ---- phase 3: aggregate (400 rows) ----
        for (int row = bid; row < BN; row += GRID) {
            const int sg = tid >> 6;        // 0..1
            const int hq = tid & 63;        // h quad
            const int b = row / N_, r = row - b * N_;
            const float* base = g_msgs + (size_t)b * E_ * H_ + hq * 4;
            float4 s = make_float4(0.f, 0.f, 0.f, 0.f);
            for (int send = sg; send < N_; send += 2) {
                if (send == r) continue;
                int e = send * 49 + r - (r > send);
                float4 v = *(const float4*)(base + (size_t)e * H_);
                s.x += v.x; s.y += v.y; s.z += v.z; s.w += v.w;
            }
            if (sg == 1) *(float4*)&part[hq * 4] = s;
            __syncthreads();
            if (sg == 0) {
                const float4 p0 = *(const float4*)&part[hq * 4];
                const float inv = 1.f / 49.f;
                float4 o;
                o.x = (s.x + p0.x) * inv;
                o.y = (s.y + p0.y) * inv;
                o.z = (s.z + p0.z) * inv;
                o.w = (s.w + p0.w) * inv;
                *(float4*)(g_agg + (size_t)row * H_ + hq * 4) = o;
            }
            __syncthreads();
        }
        gbar();

        // ---- phase 4: GRU hidden-side GEMMs (42 tiles: z 3, x 7, y 2) ----
        for (int tile = bid; tile < 42; tile += GRID) {
            int z = tile / 14, rem = tile - z * 14;
            int x = rem >> 1, y = rem & 1;
            const float* W = (z == 0) ? w_hr : (z == 1) ? w_hi : w_hh;
            tc_tile(g_agg, H_, W, H_, nullptr,
                    g_gru + (size_t)z * BN * H_, H_,
                    BN, H_, x * 64, y * 128, 0, As, Ws);
        }
        gbar();

        // ---- phase 5: GRU elementwise ----
        for (int idx = gthread; idx < BN * H_; idx += GRID * THREADS) {
            int row = idx / H_, h = idx - row * H_;
            float xr = b_ir[h], xi = b_ii[h], xn = b_in[h];
#pragma unroll
            for (int f = 0; f < IN_; f++) {
                float iv = g_ins[row * IN_ + f];
                xr += iv * w_ir[h * IN_ + f];
                xi += iv * w_ii[h * IN_ + f];
                xn += iv * w_in[h * IN_ + f];
            }
            float ar2 = g_gru[idx];
            float ai = g_gru[BN * H_ + idx];
            float ah = g_gru[2 * BN * H_ + idx];
            float r  = sigmoidf_(xr + ar2);
            float ig = sigmoidf_(xi + ai);
            float nn = tanhf(xn + r * ah);
            g_hidden[idx] = (1.f - ig) * nn + ig * g_hidden[idx];
        }
        gbar();

        // ---- phase 6: p1 = relu(hidden @ w_o1^T + b_o1) (14 tiles) ----
        for (int tile = bid; tile < 14; tile += GRID) {
            int x = tile >> 1, y = tile & 1;
            tc_tile(g_hidden, H_, w_o1, H_, b_o1, g_p1, H_,
                    BN, H_, x * 64, y * 128, 1, As, Ws);
        }
        gbar();

        // ---- phase 7: p2 = relu(p1 @ w_o2^T + b_o2) (14 tiles) ----
        for (int tile = bid; tile < 14; tile += GRID) {
            int x = tile >> 1, y = tile & 1;
            tc_tile(g_p1, H_, w_o2, H_, b_o2, g_p2, H_,
                    BN, H_, x * 64, y * 128, 1, As, Ws);
        }
        gbar();

        // ---- phase 8: pred = ins + p2 @ w_o3^T + b_o3 (400 rows) ----
        for (int row = bid; row < BN; row += GRID) {
            const int wid = tid >> 5, lane = tid & 31;
            const float* pr = g_p2 + (size_t)row * H_;
            for (int c = wid; c < IN_; c += 4) {
                const float* wr = w_o3 + (size_t)c * H_;
                float s = 0.f;
                for (int j = lane; j < H_; j += 32) s += pr[j] * wr[j];
#pragma unroll
                for (int off = 16; off; off >>= 1)
                    s += __shfl_down_sync(0xffffffffu, s, off);
                if (lane == 0) {
                    int b = row / N_, n = row % N_;
                    float v = g_ins[row * IN_ + c] + b_o3[c] + s;
                    out[(((size_t)b * T_ + t) * N_ + n) * IN_ + c] = v;
                    g_ins[row * IN_ + c] = v;
                }
            }
        }
        gbar();
    }
}

// ---------------- launch -------------------------------------------------------
extern "C" void kernel_launch(void* const* d_in, const int* in_sizes, int n_in,
                              void* d_out, int out_size) {
    const float* inputs = (const float*)d_in[0];
    const float* edges  = (const float*)d_in[1];
    const float* msg_w1 = (const float*)d_in[2];
    const float* msg_b1 = (const float*)d_in[3];
    const float* msg_w2 = (const float*)d_in[4];
    const float* msg_b2 = (const float*)d_in[5];
    const float* w_hr = (const float*)d_in[6];
    const float* w_hi = (const float*)d_in[7];
    const float* w_hh = (const float*)d_in[8];
    const float* w_ir = (const float*)d_in[9];
    const float* b_ir = (const float*)d_in[10];
    const float* w_ii = (const float*)d_in[11];
    const float* b_ii = (const float*)d_in[12];
    const float* w_in_ = (const float*)d_in[13];
    const float* b_in_ = (const float*)d_in[14];
    const float* w_o1 = (const float*)d_in[15];
    const float* b_o1 = (const float*)d_in[16];
    const float* w_o2 = (const float*)d_in[17];
    const float* b_o2 = (const float*)d_in[18];
    const float* w_o3 = (const float*)d_in[19];
    const float* b_o3 = (const float*)d_in[20];
    float* out = (float*)d_out;

    graph_rnn_persistent<<<GRID, THREADS>>>(
        inputs, edges, msg_w1, msg_b1, msg_w2, msg_b2,
        w_hr, w_hi, w_hh, w_ir, b_ir, w_ii, b_ii, w_in_, b_in_,
        w_o1, b_o1, w_o2, b_o2, w_o3, b_o3, out);
}

// round 6
// speedup vs baseline: 1.0864x; 1.0864x over previous
#include <cuda_runtime.h>
#include <math.h>

#define B_  8
#define T_  10
#define N_  50
#define IN_ 6
#define H_  256
#define K_  4
#define E_  2450           // N*(N-1)
#define BN  400            // B*N
#define BE  19600          // B*E

// ---------------- scratch (device globals) ----------------------------------
__device__ float g_hidden[BN * H_];
__device__ float g_ins[BN * IN_];
__device__ float g_U[6 * BN * H_];          // (type-1)*2 + {recv=0,send=1}
__device__ float g_msgs[BE * H_];
__device__ float g_agg[BN * H_];
__device__ float g_gru[3 * BN * H_];
__device__ float g_p1[BN * H_];
__device__ float g_p2[BN * H_];

// ---------------- helpers -----------------------------------------------------
__device__ __forceinline__ unsigned tf32c(float x) {
    unsigned r; asm("cvt.rna.tf32.f32 %0, %1;" : "=r"(r) : "f"(x)); return r;
}
__device__ __forceinline__ void mma8(float c[4], const unsigned a[4],
                                     unsigned b0, unsigned b1) {
    asm volatile(
        "mma.sync.aligned.m16n8k8.row.col.f32.tf32.tf32.f32 "
        "{%0,%1,%2,%3}, {%4,%5,%6,%7}, {%8,%9}, {%0,%1,%2,%3};"
        : "+f"(c[0]), "+f"(c[1]), "+f"(c[2]), "+f"(c[3])
        : "r"(a[0]), "r"(a[1]), "r"(a[2]), "r"(a[3]), "r"(b0), "r"(b1));
}
__device__ __forceinline__ float sigmoidf_(float x) { return 1.f / (1.f + expf(-x)); }

__device__ __forceinline__ unsigned su32(const void* p) {
    return (unsigned)__cvta_generic_to_shared(p);
}
__device__ __forceinline__ void cp16(unsigned dst, const void* src) {
    asm volatile("cp.async.ca.shared.global [%0], [%1], 16;" :: "r"(dst), "l"(src));
}
__device__ __forceinline__ void cp_commit() {
    asm volatile("cp.async.commit_group;");
}
__device__ __forceinline__ void cp_wait1() {
    asm volatile("cp.async.wait_group 1;");
}
__device__ __forceinline__ void cp_wait0() {
    asm volatile("cp.async.wait_group 0;");
}

// ---------------- cp.async 3-stage tf32 GEMM tile: 64x128, 128 threads -------
// C = A @ W^T (+bias,+relu). fp32 operands fed raw as tf32 (truncation).
__device__ void tc_tile_ca(
    const float* __restrict__ A, int lda,
    const float* __restrict__ W, int ldw,
    const float* __restrict__ bias,
    float* __restrict__ C, int ldc,
    int M, int Kdim, int row0, int col0, int act)
{
    __shared__ unsigned As[3][64][20];
    __shared__ unsigned Ws[3][128][20];

    const int tid = threadIdx.x;
    const int lane = tid & 31, wid = tid >> 5;
    const int gid = lane >> 2, tig = lane & 3;
    const int wm0 = (wid >> 1) * 32, wn0 = (wid & 1) * 64;
    const int ar = tid >> 1, akq = (tid & 1) * 8;
    const int wn = tid;

    int arow = row0 + ar; if (arow >= M) arow = M - 1;
    const float* Ap = A + (size_t)arow * lda + akq;
    const float* Wp = W + (size_t)(col0 + wn) * ldw;

    const int nch = Kdim / 16;

    // prologue: stage chunks 0,1
#pragma unroll
    for (int p = 0; p < 2; p++) {
        cp16(su32(&As[p][ar][akq]),     Ap + p * 16);
        cp16(su32(&As[p][ar][akq + 4]), Ap + p * 16 + 4);
        cp16(su32(&Ws[p][wn][0]),  Wp + p * 16);
        cp16(su32(&Ws[p][wn][4]),  Wp + p * 16 + 4);
        cp16(su32(&Ws[p][wn][8]),  Wp + p * 16 + 8);
        cp16(su32(&Ws[p][wn][12]), Wp + p * 16 + 12);
        cp_commit();
    }

    float acc[2][8][4];
#pragma unroll
    for (int mi = 0; mi < 2; mi++)
#pragma unroll
        for (int ni = 0; ni < 8; ni++)
#pragma unroll
            for (int j = 0; j < 4; j++) acc[mi][ni][j] = 0.f;

#pragma unroll 1
    for (int c = 0; c < nch; c++) {
        if (c + 1 < nch) cp_wait1(); else cp_wait0();
        __syncthreads();
        int cn = c + 2;
        if (cn < nch) {
            int bf = cn % 3;
            cp16(su32(&As[bf][ar][akq]),     Ap + cn * 16);
            cp16(su32(&As[bf][ar][akq + 4]), Ap + cn * 16 + 4);
            cp16(su32(&Ws[bf][wn][0]),  Wp + cn * 16);
            cp16(su32(&Ws[bf][wn][4]),  Wp + cn * 16 + 4);
            cp16(su32(&Ws[bf][wn][8]),  Wp + cn * 16 + 8);
            cp16(su32(&Ws[bf][wn][12]), Wp + cn * 16 + 12);
            cp_commit();
        }
        const int b = c % 3;
#pragma unroll
        for (int kk = 0; kk < 16; kk += 8) {
            unsigned a0[4], a1[4];
            a0[0] = As[b][wm0 + gid][kk + tig];
            a0[1] = As[b][wm0 + gid + 8][kk + tig];
            a0[2] = As[b][wm0 + gid][kk + tig + 4];
            a0[3] = As[b][wm0 + gid + 8][kk + tig + 4];
            a1[0] = As[b][wm0 + 16 + gid][kk + tig];
            a1[1] = As[b][wm0 + 24 + gid][kk + tig];
            a1[2] = As[b][wm0 + 16 + gid][kk + tig + 4];
            a1[3] = As[b][wm0 + 24 + gid][kk + tig + 4];
#pragma unroll
            for (int ni = 0; ni < 8; ni++) {
                int nr = wn0 + ni * 8 + gid;
                unsigned b0 = Ws[b][nr][kk + tig];
                unsigned b1 = Ws[b][nr][kk + tig + 4];
                mma8(acc[0][ni], a0, b0, b1);
                mma8(acc[1][ni], a1, b0, b1);
            }
        }
    }

#pragma unroll
    for (int mi = 0; mi < 2; mi++) {
        int r = row0 + wm0 + mi * 16 + gid;
#pragma unroll
        for (int ni = 0; ni < 8; ni++) {
            int cb = col0 + wn0 + ni * 8 + tig * 2;
            float b0 = 0.f, b1 = 0.f;
            if (bias) { b0 = bias[cb]; b1 = bias[cb + 1]; }
            float v0 = acc[mi][ni][0] + b0, v1 = acc[mi][ni][1] + b1;
            float v2 = acc[mi][ni][2] + b0, v3 = acc[mi][ni][3] + b1;
            if (act == 1) {
                v0 = fmaxf(v0, 0.f); v1 = fmaxf(v1, 0.f);
                v2 = fmaxf(v2, 0.f); v3 = fmaxf(v3, 0.f);
            }
            if (r < M)     *(float2*)(C + (size_t)r * ldc + cb)       = make_float2(v0, v1);
            if (r + 8 < M) *(float2*)(C + (size_t)(r + 8) * ldc + cb) = make_float2(v2, v3);
        }
    }
}

// ---------------- kernels ------------------------------------------------------

__global__ void init_kernel(const float* __restrict__ inputs) {
    int idx = blockIdx.x * blockDim.x + threadIdx.x;
    if (idx < BN * H_) g_hidden[idx] = 0.f;
    if (idx < BN * IN_) {
        int row = idx / IN_, c = idx % IN_;
        int b = row / N_, n = row % N_;
        g_ins[idx] = inputs[(((size_t)b * T_ + 0) * N_ + n) * IN_ + c];
    }
}

__global__ __launch_bounds__(128)
void urus_tc(const float* __restrict__ msg_w1) {
    int z = blockIdx.z;
    int it = z >> 1, rs = z & 1;
    const float* W = msg_w1 + (size_t)(it + 1) * H_ * 2 * H_ + rs * H_;
    tc_tile_ca(g_hidden, H_, W, 2 * H_, nullptr,
               g_U + (size_t)z * BN * H_, H_,
               BN, H_, blockIdx.x * 64, blockIdx.y * 128, 0);
}

// ======== fused edge-message kernel: W via cp.async, A computed+STS ==========
__global__ __launch_bounds__(128)
void msgs_tc_kernel(const float* __restrict__ msg_w2,
                    const float* __restrict__ msg_b1,
                    const float* __restrict__ msg_b2,
                    const float* __restrict__ edges, int t)
{
    __shared__ unsigned As[2][64][20];
    __shared__ unsigned Ws[3][128][20];
    __shared__ float relw[64];
    __shared__ float b2s[128];
    __shared__ int rrow[64], srow[64], eoff[64];

    const int tid = threadIdx.x;
    const int lane = tid & 31, wid = tid >> 5;
    const int gid = lane >> 2, tig = lane & 3;
    const int wm0 = (wid >> 1) * 32, wn0 = (wid & 1) * 64;
    const int row0 = blockIdx.x * 64, col0 = blockIdx.y * 128;

    if (tid < 64) {
        int r = row0 + tid;
        int valid = (r < BE);
        if (!valid) r = BE - 1;
        int b = r / E_;
        int e = r - b * E_;
        int send = e / 49, rr2 = e - send * 49;
        int recv = rr2 + (rr2 >= send);
        srow[tid] = b * N_ + send;
        rrow[tid] = b * N_ + recv;
        eoff[tid] = valid ? (((b * T_ + t) * E_ + e) * K_) : -1;
    }
    __syncthreads();

    const int ar  = tid >> 1;
    const int akq = (tid & 1) * 8;
    const int wn  = tid;

    float tot[2][8][4];
#pragma unroll
    for (int mi = 0; mi < 2; mi++)
#pragma unroll
        for (int ni = 0; ni < 8; ni++)
#pragma unroll
            for (int j = 0; j < 4; j++) tot[mi][ni][j] = 0.f;

    for (int z = 0; z < 3; z++) {
        const int type = z + 1;
        __syncthreads();   // previous type's epilogue done; smem reuse safe
        if (tid < 64)
            relw[tid] = (eoff[tid] >= 0) ? edges[eoff[tid] + type] * (1.f / 3.f) : 0.f;
        b2s[tid] = msg_b2[(size_t)type * H_ + col0 + tid];

        float acc[2][8][4];
#pragma unroll
        for (int mi = 0; mi < 2; mi++)
#pragma unroll
            for (int ni = 0; ni < 8; ni++)
#pragma unroll
                for (int j = 0; j < 4; j++) acc[mi][ni][j] = 0.f;

        const float* Ur = g_U + ((size_t)(2 * z) * BN + rrow[ar]) * H_ + akq;
        const float* Us = g_U + ((size_t)(2 * z + 1) * BN + srow[ar]) * H_ + akq;
        const float* Wb = msg_w2 + ((size_t)type * H_ + (col0 + wn)) * H_;
        const float* B1 = msg_b1 + (size_t)type * H_ + akq;

        // W prologue: chunks 0,1
#pragma unroll
        for (int p = 0; p < 2; p++) {
            cp16(su32(&Ws[p][wn][0]),  Wb + p * 16);
            cp16(su32(&Ws[p][wn][4]),  Wb + p * 16 + 4);
            cp16(su32(&Ws[p][wn][8]),  Wb + p * 16 + 8);
            cp16(su32(&Ws[p][wn][12]), Wb + p * 16 + 12);
            cp_commit();
        }

        // A regs chunk 0 -> STS A0
        float4 pu0 = *(const float4*)(Ur),     pu1 = *(const float4*)(Ur + 4);
        float4 ps0 = *(const float4*)(Us),     ps1 = *(const float4*)(Us + 4);
        float4 pb0 = *(const float4*)(B1),     pb1 = *(const float4*)(B1 + 4);
        {
            uint4 a0v, a1v;
            a0v.x = tf32c(tanhf(pu0.x + ps0.x + pb0.x));
            a0v.y = tf32c(tanhf(pu0.y + ps0.y + pb0.y));
            a0v.z = tf32c(tanhf(pu0.z + ps0.z + pb0.z));
            a0v.w = tf32c(tanhf(pu0.w + ps0.w + pb0.w));
            a1v.x = tf32c(tanhf(pu1.x + ps1.x + pb1.x));
            a1v.y = tf32c(tanhf(pu1.y + ps1.y + pb1.y));
            a1v.z = tf32c(tanhf(pu1.z + ps1.z + pb1.z));
            a1v.w = tf32c(tanhf(pu1.w + ps1.w + pb1.w));
            *(uint4*)&As[0][ar][akq]     = a0v;
            *(uint4*)&As[0][ar][akq + 4] = a1v;
        }
        // A regs chunk 1
        pu0 = *(const float4*)(Ur + 16);     pu1 = *(const float4*)(Ur + 20);
        ps0 = *(const float4*)(Us + 16);     ps1 = *(const float4*)(Us + 20);
        pb0 = *(const float4*)(B1 + 16);     pb1 = *(const float4*)(B1 + 20);

#pragma unroll 1
        for (int c = 0; c < 16; c++) {
            if (c + 1 < 16) cp_wait1(); else cp_wait0();
            __syncthreads();
            int cn = c + 2;
            if (cn < 16) {
                int bf = cn % 3;
                cp16(su32(&Ws[bf][wn][0]),  Wb + cn * 16);
                cp16(su32(&Ws[bf][wn][4]),  Wb + cn * 16 + 4);
                cp16(su32(&Ws[bf][wn][8]),  Wb + cn * 16 + 8);
                cp16(su32(&Ws[bf][wn][12]), Wb + cn * 16 + 12);
                cp_commit();
            }
            if (c + 1 < 16) {
                // STS A_{c+1} from regs (prefetched last iter)
                uint4 a0v, a1v;
                a0v.x = tf32c(tanhf(pu0.x + ps0.x + pb0.x));
                a0v.y = tf32c(tanhf(pu0.y + ps0.y + pb0.y));
                a0v.z = tf32c(tanhf(pu0.z + ps0.z + pb0.z));
                a0v.w = tf32c(tanhf(pu0.w + ps0.w + pb0.w));
                a1v.x = tf32c(tanhf(pu1.x + ps1.x + pb1.x));
                a1v.y = tf32c(tanhf(pu1.y + ps1.y + pb1.y));
                a1v.z = tf32c(tanhf(pu1.z + ps1.z + pb1.z));
                a1v.w = tf32c(tanhf(pu1.w + ps1.w + pb1.w));
                int bf = (c + 1) & 1;
                *(uint4*)&As[bf][ar][akq]     = a0v;
                *(uint4*)&As[bf][ar][akq + 4] = a1v;
            }
            if (cn < 16) {
                int k0 = cn * 16;
                pu0 = *(const float4*)(Ur + k0);     pu1 = *(const float4*)(Ur + k0 + 4);
                ps0 = *(const float4*)(Us + k0);     ps1 = *(const float4*)(Us + k0 + 4);
                pb0 = *(const float4*)(B1 + k0);     pb1 = *(const float4*)(B1 + k0 + 4);
            }
            const int ab = c & 1, wb = c % 3;
#pragma unroll
            for (int kk = 0; kk < 16; kk += 8) {
                unsigned a0[4], a1[4];
                a0[0] = As[ab][wm0 + gid][kk + tig];
                a0[1] = As[ab][wm0 + gid + 8][kk + tig];
                a0[2] = As[ab][wm0 + gid][kk + tig + 4];
                a0[3] = As[ab][wm0 + gid + 8][kk + tig + 4];
                a1[0] = As[ab][wm0 + 16 + gid][kk + tig];
                a1[1] = As[ab][wm0 + 24 + gid][kk + tig];
                a1[2] = As[ab][wm0 + 16 + gid][kk + tig + 4];
                a1[3] = As[ab][wm0 + 24 + gid][kk + tig + 4];
#pragma unroll
                for (int ni = 0; ni < 8; ni++) {
                    int nr = wn0 + ni * 8 + gid;
                    unsigned b0 = Ws[wb][nr][kk + tig];
                    unsigned b1 = Ws[wb][nr][kk + tig + 4];
                    mma8(acc[0][ni], a0, b0, b1);
                    mma8(acc[1][ni], a1, b0, b1);
                }
            }
        }

        // epilogue: tot += tanh(acc + b2) * rel
#pragma unroll
        for (int mi = 0; mi < 2; mi++) {
            float rl0 = relw[wm0 + mi * 16 + gid];
            float rl1 = relw[wm0 + mi * 16 + gid + 8];
#pragma unroll
            for (int ni = 0; ni < 8; ni++) {
                int cl = wn0 + ni * 8 + tig * 2;
                float bb0 = b2s[cl], bb1 = b2s[cl + 1];
                tot[mi][ni][0] += tanhf(acc[mi][ni][0] + bb0) * rl0;
                tot[mi][ni][1] += tanhf(acc[mi][ni][1] + bb1) * rl0;
                tot[mi][ni][2] += tanhf(acc[mi][ni][2] + bb0) * rl1;
                tot[mi][ni][3] += tanhf(acc[mi][ni][3] + bb1) * rl1;
            }
        }
    }

#pragma unroll
    for (int mi = 0; mi < 2; mi++) {
        int r = row0 + wm0 + mi * 16 + gid;
#pragma unroll
        for (int ni = 0; ni < 8; ni++) {
            int cb = col0 + wn0 + ni * 8 + tig * 2;
            if (r < BE)
                *(float2*)(g_msgs + (size_t)r * H_ + cb) =
                    make_float2(tot[mi][ni][0], tot[mi][ni][1]);
            if (r + 8 < BE)
                *(float2*)(g_msgs + (size_t)(r + 8) * H_ + cb) =
                    make_float2(tot[mi][ni][2], tot[mi][ni][3]);
        }
    }
}

// agg: grid = BN blocks, 256 threads; 4-way send split + deterministic combine
__global__ __launch_bounds__(256)
void agg_kernel() {
    __shared__ float part[3][256];
    const int tid = threadIdx.x;
    const int sg = tid >> 6;
    const int hq = tid & 63;
    const int row = blockIdx.x;
    const int b = row / N_, r = row - b * N_;
    const float* base = g_msgs + (size_t)b * E_ * H_ + hq * 4;
    float4 s = make_float4(0.f, 0.f, 0.f, 0.f);
    for (int send = sg; send < N_; send += 4) {
        if (send == r) continue;
        int e = send * 49 + r - (r > send);
        float4 v = *(const float4*)(base + (size_t)e * H_);
        s.x += v.x; s.y += v.y; s.z += v.z; s.w += v.w;
    }
    if (sg > 0) *(float4*)&part[sg - 1][hq * 4] = s;
    __syncthreads();
    if (sg == 0) {
        const float4 p0 = *(const float4*)&part[0][hq * 4];
        const float4 p1 = *(const float4*)&part[1][hq * 4];
        const float4 p2 = *(const float4*)&part[2][hq * 4];
        const float inv = 1.f / 49.f;
        float4 o;
        o.x = (s.x + p0.x + p1.x + p2.x) * inv;
        o.y = (s.y + p0.y + p1.y + p2.y) * inv;
        o.z = (s.z + p0.z + p1.z + p2.z) * inv;
        o.w = (s.w + p0.w + p1.w + p2.w) * inv;
        *(float4*)(g_agg + (size_t)row * H_ + hq * 4) = o;
    }
}

__global__ __launch_bounds__(128)
void gru_tc(const float* __restrict__ w_hr,
            const float* __restrict__ w_hi,
            const float* __restrict__ w_hh) {
    int z = blockIdx.z;
    const float* W = (z == 0) ? w_hr : (z == 1) ? w_hi : w_hh;
    tc_tile_ca(g_agg, H_, W, H_, nullptr,
               g_gru + (size_t)z * BN * H_, H_,
               BN, H_, blockIdx.x * 64, blockIdx.y * 128, 0);
}

__global__ void gruew_kernel(const float* __restrict__ w_ir, const float* __restrict__ b_ir,
                             const float* __restrict__ w_ii, const float* __restrict__ b_ii,
                             const float* __restrict__ w_in, const float* __restrict__ b_in) {
    int idx = blockIdx.x * blockDim.x + threadIdx.x;
    if (idx >= BN * H_) return;
    int row = idx / H_, h = idx - row * H_;
    float xr = b_ir[h], xi = b_ii[h], xn = b_in[h];
#pragma unroll
    for (int f = 0; f < IN_; f++) {
        float iv = g_ins[row * IN_ + f];
        xr += iv * w_ir[h * IN_ + f];
        xi += iv * w_ii[h * IN_ + f];
        xn += iv * w_in[h * IN_ + f];
    }
    float ar = g_gru[idx];
    float ai = g_gru[BN * H_ + idx];
    float ah = g_gru[2 * BN * H_ + idx];
    float r  = sigmoidf_(xr + ar);
    float ig = sigmoidf_(xi + ai);
    float nn = tanhf(xn + r * ah);
    g_hidden[idx] = (1.f - ig) * nn + ig * g_hidden[idx];
}

__global__ __launch_bounds__(128)
void p1_tc(const float* __restrict__ w_o1, const float* __restrict__ b_o1) {
    tc_tile_ca(g_hidden, H_, w_o1, H_, b_o1, g_p1, H_,
               BN, H_, blockIdx.x * 64, blockIdx.y * 128, 1);
}
__global__ __launch_bounds__(128)
void p2_tc(const float* __restrict__ w_o2, const float* __restrict__ b_o2) {
    tc_tile_ca(g_p1, H_, w_o2, H_, b_o2, g_p2, H_,
               BN, H_, blockIdx.x * 64, blockIdx.y * 128, 1);
}

__global__ void f3_kernel(const float* __restrict__ w_o3,
                          const float* __restrict__ b_o3,
                          float* __restrict__ out, int t) {
    int row = blockIdx.x;
    int w = threadIdx.x >> 5;
    int lane = threadIdx.x & 31;
    const float* pr = g_p2 + (size_t)row * H_;
    const float* wr = w_o3 + (size_t)w * H_;
    float s = 0.f;
    for (int j = lane; j < H_; j += 32) s += pr[j] * wr[j];
#pragma unroll
    for (int off = 16; off; off >>= 1) s += __shfl_down_sync(0xffffffffu, s, off);
    if (lane == 0) {
        int b = row / N_, n = row % N_;
        float v = g_ins[row * IN_ + w] + b_o3[w] + s;
        out[(((size_t)b * T_ + t) * N_ + n) * IN_ + w] = v;
        g_ins[row * IN_ + w] = v;
    }
}

// ---------------- launch -------------------------------------------------------
extern "C" void kernel_launch(void* const* d_in, const int* in_sizes, int n_in,
                              void* d_out, int out_size) {
    const float* inputs = (const float*)d_in[0];
    const float* edges  = (const float*)d_in[1];
    const float* msg_w1 = (const float*)d_in[2];
    const float* msg_b1 = (const float*)d_in[3];
    const float* msg_w2 = (const float*)d_in[4];
    const float* msg_b2 = (const float*)d_in[5];
    const float* w_hr = (const float*)d_in[6];
    const float* w_hi = (const float*)d_in[7];
    const float* w_hh = (const float*)d_in[8];
    const float* w_ir = (const float*)d_in[9];
    const float* b_ir = (const float*)d_in[10];
    const float* w_ii = (const float*)d_in[11];
    const float* b_ii = (const float*)d_in[12];
    const float* w_in_ = (const float*)d_in[13];
    const float* b_in_ = (const float*)d_in[14];
    const float* w_o1 = (const float*)d_in[15];
    const float* b_o1 = (const float*)d_in[16];
    const float* w_o2 = (const float*)d_in[17];
    const float* b_o2 = (const float*)d_in[18];
    const float* w_o3 = (const float*)d_in[19];
    const float* b_o3 = (const float*)d_in[20];
    float* out = (float*)d_out;

    init_kernel<<<(BN * H_ + 255) / 256, 256>>>(inputs);

    const int rowt = (BE + 63) / 64;  // 307
    for (int t = 0; t < T_; t++) {
        urus_tc<<<dim3(7, 2, 6), 128>>>(msg_w1);
        msgs_tc_kernel<<<dim3(rowt, 2), 128>>>(msg_w2, msg_b1, msg_b2, edges, t);
        agg_kernel<<<BN, 256>>>();
        gru_tc<<<dim3(7, 2, 3), 128>>>(w_hr, w_hi, w_hh);
        gruew_kernel<<<(BN * H_ + 255) / 256, 256>>>(w_ir, b_ir, w_ii, b_ii, w_in_, b_in_);
        p1_tc<<<dim3(7, 2), 128>>>(w_o1, b_o1);
        p2_tc<<<dim3(7, 2), 128>>>(w_o2, b_o2);
        f3_kernel<<<BN, 192>>>(w_o3, b_o3, out, t);
    }
}

// round 8
// speedup vs baseline: 1.6635x; 1.5312x over previous
#include <cuda_runtime.h>
#include <cuda_fp16.h>
#include <math.h>

#define B_  8
#define T_  10
#define N_  50
#define IN_ 6
#define H_  256
#define K_  4
#define E_  2450           // N*(N-1)
#define BN  400            // B*N
#define BE  19600          // B*E
#define HH  (H_ * H_)

// ---------------- scratch (device globals) ----------------------------------
__device__ float g_hidden[BN * H_];
__device__ __half g_hidden_h[BN * H_];
__device__ float g_ins[BN * IN_];
__device__ float g_U[6 * BN * H_];          // (type-1)*2 + {recv=0,send=1}
__device__ float g_msgs[BE * H_];
__device__ __half g_agg_h[BN * H_];
__device__ float g_gru[3 * BN * H_];
__device__ __half g_p1h[BN * H_];
__device__ float g_p2[BN * H_];

// fp16 weights (converted once per launch)
__device__ __half g_w1h[6 * HH];            // [z][n][k], z=(type-1)*2+rs
__device__ __half g_w2h[3 * HH];            // [type-1][n][k]
__device__ __half g_whh3[3 * HH];           // hr,hi,hh
__device__ __half g_wo1h[HH];
__device__ __half g_wo2h[HH];

// ---------------- helpers -----------------------------------------------------
__device__ __forceinline__ unsigned h2pack(float lo, float hi) {
    unsigned r;
    asm("cvt.rn.f16x2.f32 %0, %1, %2;" : "=r"(r) : "f"(hi), "f"(lo));
    return r;
}
__device__ __forceinline__ void mma16(float c[4], const unsigned a[4],
                                      unsigned b0, unsigned b1) {
    asm volatile(
        "mma.sync.aligned.m16n8k16.row.col.f32.f16.f16.f32 "
        "{%0,%1,%2,%3}, {%4,%5,%6,%7}, {%8,%9}, {%0,%1,%2,%3};"
        : "+f"(c[0]), "+f"(c[1]), "+f"(c[2]), "+f"(c[3])
        : "r"(a[0]), "r"(a[1]), "r"(a[2]), "r"(a[3]), "r"(b0), "r"(b1));
}
__device__ __forceinline__ float sigmoidf_(float x) { return 1.f / (1.f + expf(-x)); }

__device__ __forceinline__ unsigned su32(const void* p) {
    return (unsigned)__cvta_generic_to_shared(p);
}
__device__ __forceinline__ void cp16(unsigned dst, const void* src) {
    asm volatile("cp.async.ca.shared.global [%0], [%1], 16;" :: "r"(dst), "l"(src));
}
__device__ __forceinline__ void cp_commit() { asm volatile("cp.async.commit_group;"); }
__device__ __forceinline__ void cp_wait1() { asm volatile("cp.async.wait_group 1;"); }
__device__ __forceinline__ void cp_wait0() { asm volatile("cp.async.wait_group 0;"); }

// ---------------- one-time fp16 weight conversion ------------------------------
__global__ void cvt_weights(const float* __restrict__ msg_w1,
                            const float* __restrict__ msg_w2,
                            const float* __restrict__ w_hr,
                            const float* __restrict__ w_hi,
                            const float* __restrict__ w_hh,
                            const float* __restrict__ w_o1,
                            const float* __restrict__ w_o2) {
    int idx = blockIdx.x * blockDim.x + threadIdx.x;
    if (idx < 6 * HH) {
        int z = idx / HH, r = idx - z * HH;
        int n = r / H_, k = r - n * H_;
        int it = z >> 1, rs = z & 1;
        g_w1h[idx] = __float2half(
            msg_w1[(size_t)(it + 1) * H_ * 2 * H_ + (size_t)n * 2 * H_ + rs * H_ + k]);
    }
    if (idx < 3 * HH) {
        int i = idx / HH, r = idx - i * HH;
        g_w2h[idx] = __float2half(msg_w2[(size_t)(i + 1) * HH + r]);
    }
    if (idx < HH) {
        g_whh3[idx]          = __float2half(w_hr[idx]);
        g_whh3[HH + idx]     = __float2half(w_hi[idx]);
        g_whh3[2 * HH + idx] = __float2half(w_hh[idx]);
        g_wo1h[idx] = __float2half(w_o1[idx]);
        g_wo2h[idx] = __float2half(w_o2[idx]);
    }
}

// ---------------- fp16 m16n8k16 GEMM tile: 64x128, 128 threads, cp.async -------
// C = A @ W^T. A:[M,Kdim] fp16 row-major, W:[*,Kdim] fp16 rows (ldw). Out fp32
// (Cf) or fp16 (Ch). Rows in SMEM are 12 words (24 halves) for 16B alignment.
__device__ void tc16_tile(
    const __half* __restrict__ A, int lda,
    const __half* __restrict__ W, int ldw,
    const float* __restrict__ bias,
    float* __restrict__ Cf, __half* __restrict__ Ch, int ldc,
    int M, int Kdim, int row0, int col0, int act)
{
    __shared__ unsigned As[3][64][12];
    __shared__ unsigned Ws[3][128][12];

    const int tid = threadIdx.x;
    const int lane = tid & 31, wid = tid >> 5;
    const int gid = lane >> 2, tig = lane & 3;
    const int wm0 = (wid >> 1) * 32, wn0 = (wid & 1) * 64;
    const int ar = tid >> 1, ap = tid & 1;

    int arow = row0 + ar; if (arow >= M) arow = M - 1;
    const __half* Apt = A + (size_t)arow * lda + ap * 8;
    const __half* Wpt = W + (size_t)(col0 + tid) * ldw;

    const int nch = Kdim / 16;

#pragma unroll
    for (int p = 0; p < 2; p++) {
        cp16(su32(&As[p][ar][ap * 4]), Apt + p * 16);
        cp16(su32(&Ws[p][tid][0]), Wpt + p * 16);
        cp16(su32(&Ws[p][tid][4]), Wpt + p * 16 + 8);
        cp_commit();
    }

    float acc[2][8][4];
#pragma unroll
    for (int mi = 0; mi < 2; mi++)
#pragma unroll
        for (int ni = 0; ni < 8; ni++)
#pragma unroll
            for (int j = 0; j < 4; j++) acc[mi][ni][j] = 0.f;

#pragma unroll 1
    for (int c = 0; c < nch; c++) {
        if (c + 1 < nch) cp_wait1(); else cp_wait0();
        __syncthreads();
        int cn = c + 2;
        if (cn < nch) {
            int bf = cn % 3;
            cp16(su32(&As[bf][ar][ap * 4]), Apt + cn * 16);
            cp16(su32(&Ws[bf][tid][0]), Wpt + cn * 16);
            cp16(su32(&Ws[bf][tid][4]), Wpt + cn * 16 + 8);
            cp_commit();
        }
        const int b = c % 3;
        unsigned a0[4], a1[4];
        a0[0] = As[b][wm0 + gid][tig];
        a0[1] = As[b][wm0 + gid + 8][tig];
        a0[2] = As[b][wm0 + gid][tig + 4];
        a0[3] = As[b][wm0 + gid + 8][tig + 4];
        a1[0] = As[b][wm0 + 16 + gid][tig];
        a1[1] = As[b][wm0 + 24 + gid][tig];
        a1[2] = As[b][wm0 + 16 + gid][tig + 4];
        a1[3] = As[b][wm0 + 24 + gid][tig + 4];
#pragma unroll
        for (int ni = 0; ni < 8; ni++) {
            int nr = wn0 + ni * 8 + gid;
            unsigned b0 = Ws[b][nr][tig];
            unsigned b1 = Ws[b][nr][tig + 4];
            mma16(acc[0][ni], a0, b0, b1);
            mma16(acc[1][ni], a1, b0, b1);
        }
    }

#pragma unroll
    for (int mi = 0; mi < 2; mi++) {
        int r = row0 + wm0 + mi * 16 + gid;
#pragma unroll
        for (int ni = 0; ni < 8; ni++) {
            int cb = col0 + wn0 + ni * 8 + tig * 2;
            float b0 = 0.f, b1 = 0.f;
            if (bias) { b0 = bias[cb]; b1 = bias[cb + 1]; }
            float v0 = acc[mi][ni][0] + b0, v1 = acc[mi][ni][1] + b1;
            float v2 = acc[mi][ni][2] + b0, v3 = acc[mi][ni][3] + b1;
            if (act == 1) {
                v0 = fmaxf(v0, 0.f); v1 = fmaxf(v1, 0.f);
                v2 = fmaxf(v2, 0.f); v3 = fmaxf(v3, 0.f);
            }
            if (Cf) {
                if (r < M)     *(float2*)(Cf + (size_t)r * ldc + cb)       = make_float2(v0, v1);
                if (r + 8 < M) *(float2*)(Cf + (size_t)(r + 8) * ldc + cb) = make_float2(v2, v3);
            } else {
                if (r < M)     *(__half2*)(Ch + (size_t)r * ldc + cb)       = __floats2half2_rn(v0, v1);
                if (r + 8 < M) *(__half2*)(Ch + (size_t)(r + 8) * ldc + cb) = __floats2half2_rn(v2, v3);
            }
        }
    }
}

// ---------------- kernels ------------------------------------------------------

__global__ void init_kernel(const float* __restrict__ inputs) {
    int idx = blockIdx.x * blockDim.x + threadIdx.x;
    if (idx < BN * H_) { g_hidden[idx] = 0.f; g_hidden_h[idx] = __float2half(0.f); }
    if (idx < BN * IN_) {
        int row = idx / IN_, c = idx % IN_;
        int b = row / N_, n = row % N_;
        g_ins[idx] = inputs[(((size_t)b * T_ + 0) * N_ + n) * IN_ + c];
    }
}

__global__ __launch_bounds__(128)
void urus_tc(int dummy) {
    int z = blockIdx.z;
    tc16_tile(g_hidden_h, H_, g_w1h + (size_t)z * HH, H_, nullptr,
              g_U + (size_t)z * BN * H_, nullptr, H_,
              BN, H_, blockIdx.x * 64, blockIdx.y * 128, 0);
}

// ======== fused edge-message kernel (fp16 mma, fused tanh A-build) =============
__global__ __launch_bounds__(128)
void msgs_f16_kernel(const float* __restrict__ msg_b1,
                     const float* __restrict__ msg_b2,
                     const float* __restrict__ edges, int t)
{
    __shared__ unsigned As[2][64][12];
    __shared__ unsigned Ws[3][128][12];
    __shared__ float relw[64];
    __shared__ float b2s[128];
    __shared__ int rrow[64], srow[64], eoff[64];

    const int tid = threadIdx.x;
    const int lane = tid & 31, wid = tid >> 5;
    const int gid = lane >> 2, tig = lane & 3;
    const int wm0 = (wid >> 1) * 32, wn0 = (wid & 1) * 64;
    const int row0 = blockIdx.x * 64, col0 = blockIdx.y * 128;

    if (tid < 64) {
        int r = row0 + tid;
        int valid = (r < BE);
        if (!valid) r = BE - 1;
        int b = r / E_;
        int e = r - b * E_;
        int send = e / 49, rr2 = e - send * 49;
        int recv = rr2 + (rr2 >= send);
        srow[tid] = b * N_ + send;
        rrow[tid] = b * N_ + recv;
        eoff[tid] = valid ? (((b * T_ + t) * E_ + e) * K_) : -1;
    }
    __syncthreads();

    const int ar = tid >> 1, ap = tid & 1;

    float tot[2][8][4];
#pragma unroll
    for (int mi = 0; mi < 2; mi++)
#pragma unroll
        for (int ni = 0; ni < 8; ni++)
#pragma unroll
            for (int j = 0; j < 4; j++) tot[mi][ni][j] = 0.f;

    for (int z = 0; z < 3; z++) {
        const int type = z + 1;
        __syncthreads();   // previous type done with smem
        if (tid < 64)
            relw[tid] = (eoff[tid] >= 0) ? edges[eoff[tid] + type] * (1.f / 3.f) : 0.f;
        b2s[tid] = msg_b2[(size_t)type * H_ + col0 + tid];

        float acc[2][8][4];
#pragma unroll
        for (int mi = 0; mi < 2; mi++)
#pragma unroll
            for (int ni = 0; ni < 8; ni++)
#pragma unroll
                for (int j = 0; j < 4; j++) acc[mi][ni][j] = 0.f;

        const float*  Urb = g_U + ((size_t)(2 * z) * BN + rrow[ar]) * H_ + ap * 8;
        const float*  Usb = g_U + ((size_t)(2 * z + 1) * BN + srow[ar]) * H_ + ap * 8;
        const float*  B1b = msg_b1 + (size_t)type * H_ + ap * 8;
        const __half* Wb  = g_w2h + ((size_t)z * H_ + (col0 + tid)) * H_;

        // W prologue: chunks 0,1
#pragma unroll
        for (int p = 0; p < 2; p++) {
            cp16(su32(&Ws[p][tid][0]), Wb + p * 16);
            cp16(su32(&Ws[p][tid][4]), Wb + p * 16 + 8);
            cp_commit();
        }

        // A chunk 0: compute tanh + pack + STS
        float4 pu0 = *(const float4*)(Urb),     pu1 = *(const float4*)(Urb + 4);
        float4 ps0 = *(const float4*)(Usb),     ps1 = *(const float4*)(Usb + 4);
        float4 pb0 = *(const float4*)(B1b),     pb1 = *(const float4*)(B1b + 4);
        {
            uint4 v;
            v.x = h2pack(tanhf(pu0.x + ps0.x + pb0.x), tanhf(pu0.y + ps0.y + pb0.y));
            v.y = h2pack(tanhf(pu0.z + ps0.z + pb0.z), tanhf(pu0.w + ps0.w + pb0.w));
            v.z = h2pack(tanhf(pu1.x + ps1.x + pb1.x), tanhf(pu1.y + ps1.y + pb1.y));
            v.w = h2pack(tanhf(pu1.z + ps1.z + pb1.z), tanhf(pu1.w + ps1.w + pb1.w));
            *(uint4*)&As[0][ar][ap * 4] = v;
        }
        // prefetch A regs for chunk 1
        pu0 = *(const float4*)(Urb + 16); pu1 = *(const float4*)(Urb + 20);
        ps0 = *(const float4*)(Usb + 16); ps1 = *(const float4*)(Usb + 20);
        pb0 = *(const float4*)(B1b + 16); pb1 = *(const float4*)(B1b + 20);

#pragma unroll 1
        for (int c = 0; c < 16; c++) {
            if (c + 1 < 16) cp_wait1(); else cp_wait0();
            __syncthreads();
            int cn = c + 2;
            if (cn < 16) {
                int bf = cn % 3;
                cp16(su32(&Ws[bf][tid][0]), Wb + cn * 16);
                cp16(su32(&Ws[bf][tid][4]), Wb + cn * 16 + 8);
                cp_commit();
            }
            if (c + 1 < 16) {
                uint4 v;
                v.x = h2pack(tanhf(pu0.x + ps0.x + pb0.x), tanhf(pu0.y + ps0.y + pb0.y));
                v.y = h2pack(tanhf(pu0.z + ps0.z + pb0.z), tanhf(pu0.w + ps0.w + pb0.w));
                v.z = h2pack(tanhf(pu1.x + ps1.x + pb1.x), tanhf(pu1.y + ps1.y + pb1.y));
                v.w = h2pack(tanhf(pu1.z + ps1.z + pb1.z), tanhf(pu1.w + ps1.w + pb1.w));
                *(uint4*)&As[(c + 1) & 1][ar][ap * 4] = v;
            }
            if (cn < 16) {
                int k0 = cn * 16;
                pu0 = *(const float4*)(Urb + k0); pu1 = *(const float4*)(Urb + k0 + 4);
                ps0 = *(const float4*)(Usb + k0); ps1 = *(const float4*)(Usb + k0 + 4);
                pb0 = *(const float4*)(B1b + k0); pb1 = *(const float4*)(B1b + k0 + 4);
            }
            const int ab = c & 1, wb = c % 3;
            unsigned a0[4], a1[4];
            a0[0] = As[ab][wm0 + gid][tig];
            a0[1] = As[ab][wm0 + gid + 8][tig];
            a0[2] = As[ab][wm0 + gid][tig + 4];
            a0[3] = As[ab][wm0 + gid + 8][tig + 4];
            a1[0] = As[ab][wm0 + 16 + gid][tig];
            a1[1] = As[ab][wm0 + 24 + gid][tig];
            a1[2] = As[ab][wm0 + 16 + gid][tig + 4];
            a1[3] = As[ab][wm0 + 24 + gid][tig + 4];
#pragma unroll
            for (int ni = 0; ni < 8; ni++) {
                int nr = wn0 + ni * 8 + gid;
                unsigned b0 = Ws[wb][nr][tig];
                unsigned b1 = Ws[wb][nr][tig + 4];
                mma16(acc[0][ni], a0, b0, b1);
                mma16(acc[1][ni], a1, b0, b1);
            }
        }

        // epilogue: tot += tanh(acc + b2) * rel
#pragma unroll
        for (int mi = 0; mi < 2; mi++) {
            float rl0 = relw[wm0 + mi * 16 + gid];
            float rl1 = relw[wm0 + mi * 16 + gid + 8];
#pragma unroll
            for (int ni = 0; ni < 8; ni++) {
                int cl = wn0 + ni * 8 + tig * 2;
                float bb0 = b2s[cl], bb1 = b2s[cl + 1];
                tot[mi][ni][0] += tanhf(acc[mi][ni][0] + bb0) * rl0;
                tot[mi][ni][1] += tanhf(acc[mi][ni][1] + bb1) * rl0;
                tot[mi][ni][2] += tanhf(acc[mi][ni][2] + bb0) * rl1;
                tot[mi][ni][3] += tanhf(acc[mi][ni][3] + bb1) * rl1;
            }
        }
    }

#pragma unroll
    for (int mi = 0; mi < 2; mi++) {
        int r = row0 + wm0 + mi * 16 + gid;
#pragma unroll
        for (int ni = 0; ni < 8; ni++) {
            int cb = col0 + wn0 + ni * 8 + tig * 2;
            if (r < BE)
                *(float2*)(g_msgs + (size_t)r * H_ + cb) =
                    make_float2(tot[mi][ni][0], tot[mi][ni][1]);
            if (r + 8 < BE)
                *(float2*)(g_msgs + (size_t)(r + 8) * H_ + cb) =
                    make_float2(tot[mi][ni][2], tot[mi][ni][3]);
        }
    }
}

// agg: fp32 gather-sum -> fp16 output for the GRU GEMMs
__global__ __launch_bounds__(256)
void agg_kernel() {
    __shared__ float part[3][256];
    const int tid = threadIdx.x;
    const int sg = tid >> 6;
    const int hq = tid & 63;
    const int row = blockIdx.x;
    const int b = row / N_, r = row - b * N_;
    const float* base = g_msgs + (size_t)b * E_ * H_ + hq * 4;
    float4 s = make_float4(0.f, 0.f, 0.f, 0.f);
    for (int send = sg; send < N_; send += 4) {
        if (send == r) continue;
        int e = send * 49 + r - (r > send);
        float4 v = *(const float4*)(base + (size_t)e * H_);
        s.x += v.x; s.y += v.y; s.z += v.z; s.w += v.w;
    }
    if (sg > 0) *(float4*)&part[sg - 1][hq * 4] = s;
    __syncthreads();
    if (sg == 0) {
        const float4 p0 = *(const float4*)&part[0][hq * 4];
        const float4 p1 = *(const float4*)&part[1][hq * 4];
        const float4 p2 = *(const float4*)&part[2][hq * 4];
        const float inv = 1.f / 49.f;
        float4 o;
        o.x = (s.x + p0.x + p1.x + p2.x) * inv;
        o.y = (s.y + p0.y + p1.y + p2.y) * inv;
        o.z = (s.z + p0.z + p1.z + p2.z) * inv;
        o.w = (s.w + p0.w + p1.w + p2.w) * inv;
        __half2 h01 = __floats2half2_rn(o.x, o.y);
        __half2 h23 = __floats2half2_rn(o.z, o.w);
        *(__half2*)(g_agg_h + (size_t)row * H_ + hq * 4)     = h01;
        *(__half2*)(g_agg_h + (size_t)row * H_ + hq * 4 + 2) = h23;
    }
}

__global__ __launch_bounds__(128)
void gru_tc(int dummy) {
    int z = blockIdx.z;
    tc16_tile(g_agg_h, H_, g_whh3 + (size_t)z * HH, H_, nullptr,
              g_gru + (size_t)z * BN * H_, nullptr, H_,
              BN, H_, blockIdx.x * 64, blockIdx.y * 128, 0);
}

__global__ void gruew_kernel(const float* __restrict__ w_ir, const float* __restrict__ b_ir,
                             const float* __restrict__ w_ii, const float* __restrict__ b_ii,
                             const float* __restrict__ w_in, const float* __restrict__ b_in) {
    int idx = blockIdx.x * blockDim.x + threadIdx.x;
    if (idx >= BN * H_) return;
    int row = idx / H_, h = idx - row * H_;
    float xr = b_ir[h], xi = b_ii[h], xn = b_in[h];
#pragma unroll
    for (int f = 0; f < IN_; f++) {
        float iv = g_ins[row * IN_ + f];
        xr += iv * w_ir[h * IN_ + f];
        xi += iv * w_ii[h * IN_ + f];
        xn += iv * w_in[h * IN_ + f];
    }
    float ar = g_gru[idx];
    float ai = g_gru[BN * H_ + idx];
    float ah = g_gru[2 * BN * H_ + idx];
    float r  = sigmoidf_(xr + ar);
    float ig = sigmoidf_(xi + ai);
    float nn = tanhf(xn + r * ah);
    float hnew = (1.f - ig) * nn + ig * g_hidden[idx];
    g_hidden[idx] = hnew;
    g_hidden_h[idx] = __float2half(hnew);
}

__global__ __launch_bounds__(128)
void p1_tc(const float* __restrict__ b_o1) {
    tc16_tile(g_hidden_h, H_, g_wo1h, H_, b_o1, nullptr, g_p1h, H_,
              BN, H_, blockIdx.x * 64, blockIdx.y * 128, 1);
}
__global__ __launch_bounds__(128)
void p2_tc(const float* __restrict__ b_o2) {
    tc16_tile(g_p1h, H_, g_wo2h, H_, b_o2, g_p2, nullptr, H_,
              BN, H_, blockIdx.x * 64, blockIdx.y * 128, 1);
}

__global__ void f3_kernel(const float* __restrict__ w_o3,
                          const float* __restrict__ b_o3,
                          float* __restrict__ out, int t) {
    int row = blockIdx.x;
    int w = threadIdx.x >> 5;
    int lane = threadIdx.x & 31;
    const float* pr = g_p2 + (size_t)row * H_;
    const float* wr = w_o3 + (size_t)w * H_;
    float s = 0.f;
    for (int j = lane; j < H_; j += 32) s += pr[j] * wr[j];
#pragma unroll
    for (int off = 16; off; off >>= 1) s += __shfl_down_sync(0xffffffffu, s, off);
    if (lane == 0) {
        int b = row / N_, n = row % N_;
        float v = g_ins[row * IN_ + w] + b_o3[w] + s;
        out[(((size_t)b * T_ + t) * N_ + n) * IN_ + w] = v;
        g_ins[row * IN_ + w] = v;
    }
}

// ---------------- launch ---------------------------------------------------------
extern "C" void kernel_launch(void* const* d_in, const int* in_sizes, int n_in,
                              void* d_out, int out_size) {
    const float* inputs = (const float*)d_in[0];
    const float* edges  = (const float*)d_in[1];
    const float* msg_w1 = (const float*)d_in[2];
    const float* msg_b1 = (const float*)d_in[3];
    const float* msg_w2 = (const float*)d_in[4];
    const float* msg_b2 = (const float*)d_in[5];
    const float* w_hr = (const float*)d_in[6];
    const float* w_hi = (const float*)d_in[7];
    const float* w_hh = (const float*)d_in[8];
    const float* w_ir = (const float*)d_in[9];
    const float* b_ir = (const float*)d_in[10];
    const float* w_ii = (const float*)d_in[11];
    const float* b_ii = (const float*)d_in[12];
    const float* w_in_ = (const float*)d_in[13];
    const float* b_in_ = (const float*)d_in[14];
    const float* w_o1 = (const float*)d_in[15];
    const float* b_o1 = (const float*)d_in[16];
    const float* w_o2 = (const float*)d_in[17];
    const float* b_o2 = (const float*)d_in[18];
    const float* w_o3 = (const float*)d_in[19];
    const float* b_o3 = (const float*)d_in[20];
    float* out = (float*)d_out;

    cvt_weights<<<(6 * HH + 255) / 256, 256>>>(msg_w1, msg_w2, w_hr, w_hi, w_hh,
                                               w_o1, w_o2);
    init_kernel<<<(BN * H_ + 255) / 256, 256>>>(inputs);

    const int rowt = (BE + 63) / 64;  // 307
    for (int t = 0; t < T_; t++) {
        urus_tc<<<dim3(7, 2, 6), 128>>>(0);
        msgs_f16_kernel<<<dim3(rowt, 2), 128>>>(msg_b1, msg_b2, edges, t);
        agg_kernel<<<BN, 256>>>();
        gru_tc<<<dim3(7, 2, 3), 128>>>(0);
        gruew_kernel<<<(BN * H_ + 255) / 256, 256>>>(w_ir, b_ir, w_ii, b_ii, w_in_, b_in_);
        p1_tc<<<dim3(7, 2), 128>>>(b_o1);
        p2_tc<<<dim3(7, 2), 128>>>(b_o2);
        f3_kernel<<<BN, 192>>>(w_o3, b_o3, out, t);
    }
}